// round 1
// baseline (speedup 1.0000x reference)
#include <cuda_runtime.h>
#include <cuda_bf16.h>

// ---------------------------------------------------------------------------
// Attention3D: B=2, D=8,H=16,W=32 -> N=4096, C=128, heads=4, dim_head=32
// cosine attention, SCALE=10. All fp32.
// ---------------------------------------------------------------------------

#define B_   2
#define N_   4096
#define C_   128
#define NH   4
#define DH   32
#define DIM  128          // NH*DH
#define QKV  384          // 3*DIM
#define ROWS_TOT (B_*N_)  // 8192

// SCALE * log2(e)
#define C0 14.4269504088896340736f

// ---------------- scratch (no allocations allowed) -------------------------
__device__ __align__(16) float g_q[B_*NH*N_*DH];   // [bh][n][d], pre-scaled by SCALE*log2e
__device__ __align__(16) float g_k[B_*NH*N_*DH];   // [bh][n][d], unit norm
__device__ __align__(16) float g_v[B_*NH*N_*DH];   // [bh][n][d]
__device__ __align__(16) float g_ao[B_*N_*DIM];    // attention output [b][n][h*32+d]

// ---------------- packed f32x2 helpers -------------------------------------
__device__ __forceinline__ unsigned long long pack2(float a, float b) {
    unsigned long long r;
    asm("mov.b64 %0, {%1,%2};" : "=l"(r) : "f"(a), "f"(b));
    return r;
}
__device__ __forceinline__ float2 unpack2(unsigned long long v) {
    float2 f;
    asm("mov.b64 {%0,%1}, %2;" : "=f"(f.x), "=f"(f.y) : "l"(v));
    return f;
}
__device__ __forceinline__ unsigned long long ffma2(unsigned long long a,
                                                    unsigned long long b,
                                                    unsigned long long c) {
    unsigned long long d;
    asm("fma.rn.f32x2 %0, %1, %2, %3;" : "=l"(d) : "l"(a), "l"(b), "l"(c));
    return d;
}
__device__ __forceinline__ float ex2(float x) {
    float r;
    asm("ex2.approx.ftz.f32 %0, %1;" : "=f"(r) : "f"(x));
    return r;
}

// ---------------------------------------------------------------------------
// Kernel A: qkv = x @ w_qkv, then per-head L2 norm of q,k.
// 128 blocks x 192 threads; each block caches full w_qkv (196KB) in smem and
// streams 64 rows. Thread j owns column pair (2j, 2j+1).
// ---------------------------------------------------------------------------
__global__ void __launch_bounds__(192) qkv_kernel(const float* __restrict__ x,
                                                  const float* __restrict__ w) {
    extern __shared__ float smA[];
    float* ws = smA;                                            // 49152 floats
    unsigned long long* xu = (unsigned long long*)(smA + C_*QKV); // 2*128 ull

    const int tid = threadIdx.x;

    // cooperative load of w_qkv into smem (coalesced float4)
    const float4* w4 = (const float4*)w;
    float4* ws4 = (float4*)ws;
    for (int i = tid; i < (C_*QKV)/4; i += 192) ws4[i] = w4[i];
    __syncthreads();

    const unsigned long long* wsu = (const unsigned long long*)ws; // [c][192] pairs
    const int j = tid;

    for (int r = 0; r < 64; ++r) {
        const int row = blockIdx.x * 64 + r;
        // warp0 stages the x row, duplicated into f32x2 lanes
        if (tid < 32) {
            float4 v = ((const float4*)(x + (size_t)row * C_))[tid];
            int base = (r & 1) * 128 + tid * 4;
            xu[base+0] = pack2(v.x, v.x);
            xu[base+1] = pack2(v.y, v.y);
            xu[base+2] = pack2(v.z, v.z);
            xu[base+3] = pack2(v.w, v.w);
        }
        __syncthreads();
        const unsigned long long* xb = xu + (r & 1) * 128;

        unsigned long long acc = 0ULL;
        #pragma unroll 8
        for (int c = 0; c < C_; ++c)
            acc = ffma2(xb[c], wsu[c * 192 + j], acc);
        float2 a = unpack2(acc);

        const int b = row >> 12;
        const int n = row & (N_ - 1);

        if (j < 128) {
            // q (j<64) or k (64<=j<128): per-head L2 norm over 16-lane group
            float ss = a.x * a.x + a.y * a.y;
            #pragma unroll
            for (int o = 8; o; o >>= 1)
                ss += __shfl_xor_sync(0xffffffffu, ss, o, 16);
            float inv = 1.0f / fmaxf(sqrtf(ss), 1e-12f);
            if (j < 64) inv *= C0;          // bake SCALE*log2e into q
            const int jj = j & 63;
            const int h  = jj >> 4;
            const int d  = (jj & 15) * 2;
            float* dst = (j < 64 ? g_q : g_k) + (((size_t)(b*NH + h) * N_ + n) * DH + d);
            *(float2*)dst = make_float2(a.x * inv, a.y * inv);
        } else {
            const int jj = j - 128;
            const int h  = jj >> 4;
            const int d  = (jj & 15) * 2;
            *(float2*)(g_v + (((size_t)(b*NH + h) * N_ + n) * DH + d)) =
                make_float2(a.x, a.y);
        }
    }
}

// ---------------------------------------------------------------------------
// Kernel B: flash attention with fixed softmax offset (scores bounded by 10).
// grid (32 q-tiles, 8 bh), 128 threads; one query row per thread.
// KV tiles of 128 keys staged in smem; inner loops are f32x2 FMA with
// broadcast LDS.128 reads of the shared key/value row.
// ---------------------------------------------------------------------------
__global__ void __launch_bounds__(128) attn_kernel() {
    __shared__ __align__(16) float sK[128 * DH];
    __shared__ __align__(16) float sV[128 * DH];

    const int bh  = blockIdx.y;
    const int row = blockIdx.x * 128 + threadIdx.x;

    // load this thread's q row (pre-scaled by SCALE*log2e)
    unsigned long long q[16];
    {
        const ulonglong2* q2 = (const ulonglong2*)(g_q + ((size_t)bh * N_ + row) * DH);
        #pragma unroll
        for (int i = 0; i < 8; ++i) { ulonglong2 t = q2[i]; q[2*i] = t.x; q[2*i+1] = t.y; }
    }

    unsigned long long o[16];
    #pragma unroll
    for (int i = 0; i < 16; ++i) o[i] = 0ULL;
    float l = 0.f;

    const float4* Kb = (const float4*)(g_k + (size_t)bh * N_ * DH);
    const float4* Vb = (const float4*)(g_v + (size_t)bh * N_ * DH);

    for (int t = 0; t < N_ / 128; ++t) {
        __syncthreads();
        #pragma unroll
        for (int i = 0; i < 8; ++i) {
            ((float4*)sK)[threadIdx.x + i*128] = Kb[t*1024 + threadIdx.x + i*128];
            ((float4*)sV)[threadIdx.x + i*128] = Vb[t*1024 + threadIdx.x + i*128];
        }
        __syncthreads();

        #pragma unroll 2
        for (int jj = 0; jj < 128; ++jj) {
            const ulonglong2* kr = (const ulonglong2*)(sK + jj * DH);
            unsigned long long a0 = 0ULL, a1 = 0ULL;
            #pragma unroll
            for (int i = 0; i < 4; ++i) {
                ulonglong2 k0 = kr[2*i], k1 = kr[2*i+1];
                a0 = ffma2(q[4*i+0], k0.x, a0);
                a1 = ffma2(q[4*i+1], k0.y, a1);
                a0 = ffma2(q[4*i+2], k1.x, a0);
                a1 = ffma2(q[4*i+3], k1.y, a1);
            }
            float2 f0 = unpack2(a0), f1 = unpack2(a1);
            float s = (f0.x + f0.y) + (f1.x + f1.y);   // = 10*log2e*cos(q,k)
            float p = ex2(s - C0);                     // exp(score - 10)
            l += p;
            unsigned long long pp = pack2(p, p);
            const ulonglong2* vr = (const ulonglong2*)(sV + jj * DH);
            #pragma unroll
            for (int i = 0; i < 8; ++i) {
                ulonglong2 vv = vr[i];
                o[2*i]   = ffma2(pp, vv.x, o[2*i]);
                o[2*i+1] = ffma2(pp, vv.y, o[2*i+1]);
            }
        }
    }

    const float inv = 1.0f / l;
    const int b = bh >> 2, h = bh & 3;
    float* op = g_ao + ((size_t)(b * N_) + row) * DIM + h * DH;
    #pragma unroll
    for (int i = 0; i < 16; ++i) {
        float2 f = unpack2(o[i]);
        ((float2*)op)[i] = make_float2(f.x * inv, f.y * inv);
    }
}

// ---------------------------------------------------------------------------
// Kernel C: out = g_ao @ w_out + b_out.  128 blocks x 128 threads, w_out in
// smem (64KB dynamic), 64 rows per block, thread j owns output column j.
// ---------------------------------------------------------------------------
__global__ void __launch_bounds__(128) out_kernel(const float* __restrict__ wout,
                                                  const float* __restrict__ bout,
                                                  float* __restrict__ out) {
    extern __shared__ float smC[];
    float* ws = smC;                 // 16384 floats
    float* xb = smC + DIM * DIM;     // 2*128 floats

    const int tid = threadIdx.x;
    const float4* w4 = (const float4*)wout;
    float4* ws4 = (float4*)ws;
    for (int i = tid; i < (DIM*DIM)/4; i += 128) ws4[i] = w4[i];
    const float bj = bout[tid];
    __syncthreads();

    for (int r = 0; r < 64; ++r) {
        const int row = blockIdx.x * 64 + r;
        if (tid < 32)
            ((float4*)(xb + (r & 1) * 128))[tid] =
                ((const float4*)(g_ao + (size_t)row * DIM))[tid];
        __syncthreads();
        const float* xs = xb + (r & 1) * 128;
        float acc = bj;
        #pragma unroll 8
        for (int c = 0; c < DIM; ++c)
            acc = fmaf(xs[c], ws[c * DIM + tid], acc);
        out[(size_t)row * DIM + tid] = acc;
    }
}

// ---------------------------------------------------------------------------
extern "C" void kernel_launch(void* const* d_in, const int* in_sizes, int n_in,
                              void* d_out, int out_size) {
    // identify inputs by element count (robust to ordering)
    const float* x = nullptr, *wqkv = nullptr, *wout = nullptr, *bout = nullptr;
    for (int i = 0; i < n_in; ++i) {
        switch (in_sizes[i]) {
            case ROWS_TOT * C_: x    = (const float*)d_in[i]; break; // 1048576*? = 8192*128
            case C_ * QKV:      wqkv = (const float*)d_in[i]; break; // 49152
            case DIM * C_:      wout = (const float*)d_in[i]; break; // 16384
            case C_:            bout = (const float*)d_in[i]; break; // 128
        }
    }
    float* out = (float*)d_out;

    const int smA = C_ * QKV * 4 + 256 * 8;       // 198656 B
    const int smC = DIM * DIM * 4 + 256 * 4;      // 66560 B
    cudaFuncSetAttribute(qkv_kernel, cudaFuncAttributeMaxDynamicSharedMemorySize, smA);
    cudaFuncSetAttribute(out_kernel, cudaFuncAttributeMaxDynamicSharedMemorySize, smC);

    qkv_kernel<<<128, 192, smA>>>(x, wqkv);
    attn_kernel<<<dim3(32, 8), 128>>>();
    out_kernel<<<128, 128, smC>>>(wout, bout, out);
}